// round 13
// baseline (speedup 1.0000x reference)
#include <cuda_runtime.h>
#include <cmath>

// Problem constants
#define S_LEN    2048
#define D_MODEL  1024
#define NHEADS   16
#define DH       64
#define QKV_LD   3072   // 3*D
#define NTOK     4096   // B*S

// Scratch (module-static device globals)
__device__ unsigned g_qkv[(size_t)NTOK * QKV_LD];      // tf32 bits; V third unused
__device__ unsigned g_vt[(size_t)2 * NHEADS * DH * S_LEN]; // tf32 bits V^T [b,h,d,seq]
__device__ unsigned g_attn[(size_t)NTOK * D_MODEL];    // tf32-bit attention output
__device__ unsigned g_xt[(size_t)NTOK * D_MODEL];      // tf32-bit x
__device__ unsigned g_wqkvt[(size_t)D_MODEL * QKV_LD]; // tf32-bit Wqkv^T [3072][1024]
__device__ unsigned g_woutt[(size_t)D_MODEL * D_MODEL];// tf32-bit Wout^T [1024][1024]

// ---------------------------------------------------------------------------
// helpers
// ---------------------------------------------------------------------------
__device__ __forceinline__ unsigned f2tf32(float x) {
    unsigned u;
    asm("cvt.rna.tf32.f32 %0, %1;" : "=r"(u) : "f"(x));
    return u;
}

__device__ __forceinline__ void mma_tf32(float* c, const unsigned* a, const unsigned* b) {
    asm volatile(
        "mma.sync.aligned.m16n8k8.row.col.f32.tf32.tf32.f32 "
        "{%0,%1,%2,%3}, {%4,%5,%6,%7}, {%8,%9}, {%0,%1,%2,%3};"
        : "+f"(c[0]), "+f"(c[1]), "+f"(c[2]), "+f"(c[3])
        : "r"(a[0]), "r"(a[1]), "r"(a[2]), "r"(a[3]), "r"(b[0]), "r"(b[1]));
}

__device__ __forceinline__ void ldsm_x4(unsigned& r0, unsigned& r1, unsigned& r2,
                                        unsigned& r3, unsigned addr) {
    asm volatile("ldmatrix.sync.aligned.m8n8.x4.shared.b16 {%0,%1,%2,%3}, [%4];"
                 : "=r"(r0), "=r"(r1), "=r"(r2), "=r"(r3) : "r"(addr));
}

__device__ __forceinline__ void cp_async16(unsigned smem_addr, const void* gptr) {
    asm volatile("cp.async.cg.shared.global [%0], [%1], 16;"
                 :: "r"(smem_addr), "l"(gptr));
}
__device__ __forceinline__ void cp_commit() { asm volatile("cp.async.commit_group;"); }
__device__ __forceinline__ void cp_wait0()  { asm volatile("cp.async.wait_group 0;"); }

// ---------------------------------------------------------------------------
// Pre-pass kernels: tf32 convert (x) and tf32 convert + transpose (weights)
// ---------------------------------------------------------------------------
__global__ void cvt_tf32_kernel(const float4* __restrict__ src,
                                uint4* __restrict__ dst, int n4) {
    int i = blockIdx.x * blockDim.x + threadIdx.x;
    if (i < n4) {
        float4 v = src[i];
        dst[i] = make_uint4(f2tf32(v.x), f2tf32(v.y), f2tf32(v.z), f2tf32(v.w));
    }
}

// src [K][N] fp32 -> dst [N][K] tf32 bits; K,N multiples of 32; 256 threads
__global__ void cvt_t_tf32_kernel(const float* __restrict__ src,
                                  unsigned* __restrict__ dst, int K, int N) {
    __shared__ unsigned sm[32][33];
    const int tx = threadIdx.x & 31, ty = threadIdx.x >> 5;   // 32 x 8
    const int k0 = blockIdx.y * 32, n0 = blockIdx.x * 32;
#pragma unroll
    for (int i = 0; i < 4; i++) {
        int rr = ty + 8 * i;
        sm[tx][rr] = f2tf32(src[(size_t)(k0 + rr) * N + n0 + tx]);
    }
    __syncthreads();
#pragma unroll
    for (int i = 0; i < 4; i++) {
        int rr = ty + 8 * i;
        dst[(size_t)(n0 + rr) * K + k0 + tx] = sm[rr][tx];
    }
}

// ---------------------------------------------------------------------------
// tf32 tensor-core GEMM + bias; A [M][K] tf32 bits, B TRANSPOSED [N][K] tf32 bits.
// cp.async double-buffered; fragments via ldmatrix.x4. (validated R11)
// MODE 0: fp32 out. MODE 1: qkv writer — q/k thirds -> tf32 bits in C,
//         V third -> tf32 bits TRANSPOSED into vt[b,h,d,seq].
// ---------------------------------------------------------------------------
#define TS_W 36
#define BUF_WORDS (2 * 128 * TS_W)           // 9216 words per stage
#define GEMM_SMEM_BYTES (2 * BUF_WORDS * 4)  // 73728

template<int MODE>
__global__ __launch_bounds__(256, 2)
void tf32_gemm_bias(const unsigned* __restrict__ A, const unsigned* __restrict__ Bt,
                    const float* __restrict__ bias, void* __restrict__ Cv,
                    unsigned* __restrict__ vt,
                    int M, int N, int K) {
    extern __shared__ unsigned gsm[];

    const int tid  = threadIdx.x;
    const int warp = tid >> 5, lane = tid & 31;
    const int gid  = lane >> 2, tig = lane & 3;
    const int q8   = lane >> 3, r8 = lane & 7;
    const int wrow = warp >> 1, wcol = warp & 1;
    const int bm = blockIdx.y, bn = blockIdx.x;

    int lrow[4], lcol[4];
#pragma unroll
    for (int c = 0; c < 4; c++) {
        int idx4 = tid + c * 256;
        lrow[c] = idx4 >> 3;  lcol[c] = (idx4 & 7) * 4;
    }

    const unsigned smem_base = (unsigned)__cvta_generic_to_shared(gsm);

    auto issue_tile = [&](int s, int k0) {
        unsigned as_b = smem_base + (unsigned)(s * BUF_WORDS) * 4u;
        unsigned bs_b = as_b + 128u * TS_W * 4u;
#pragma unroll
        for (int c = 0; c < 4; c++) {
            cp_async16(as_b + (unsigned)(lrow[c] * TS_W + lcol[c]) * 4u,
                       A + (size_t)(bm * 128 + lrow[c]) * K + k0 + lcol[c]);
            cp_async16(bs_b + (unsigned)(lrow[c] * TS_W + lcol[c]) * 4u,
                       Bt + (size_t)(bn * 128 + lrow[c]) * K + k0 + lcol[c]);
        }
        cp_commit();
    };

    unsigned aOff[2], bOff[4];
#pragma unroll
    for (int mt = 0; mt < 2; mt++)
        aOff[mt] = (unsigned)(((wrow * 32 + mt * 16 + r8 + (q8 & 1) * 8) * TS_W
                              + (q8 >> 1) * 4) * 4);
#pragma unroll
    for (int p = 0; p < 4; p++)
        bOff[p] = (unsigned)((128 * TS_W
                              + (wcol * 64 + p * 16 + r8 + (q8 >> 1) * 8) * TS_W
                              + (q8 & 1) * 4) * 4);

    float acc[2][8][4];
#pragma unroll
    for (int mt = 0; mt < 2; mt++)
#pragma unroll
        for (int nt = 0; nt < 8; nt++)
#pragma unroll
            for (int i = 0; i < 4; i++) acc[mt][nt][i] = 0.f;

    issue_tile(0, 0);

    int s = 0;
    for (int k0 = 0; k0 < K; k0 += 32) {
        cp_wait0();
        __syncthreads();
        if (k0 + 32 < K) issue_tile(s ^ 1, k0 + 32);

        const unsigned stage = smem_base + (unsigned)(s * BUF_WORDS) * 4u;

#pragma unroll
        for (int ks = 0; ks < 4; ks++) {
            unsigned af[2][4];
            ldsm_x4(af[0][0], af[0][1], af[0][2], af[0][3], stage + aOff[0] + ks * 32);
            ldsm_x4(af[1][0], af[1][1], af[1][2], af[1][3], stage + aOff[1] + ks * 32);
            unsigned bf[8][2];
#pragma unroll
            for (int p = 0; p < 4; p++)
                ldsm_x4(bf[2*p][0], bf[2*p][1], bf[2*p+1][0], bf[2*p+1][1],
                        stage + bOff[p] + ks * 32);
#pragma unroll
            for (int mt = 0; mt < 2; mt++)
#pragma unroll
                for (int nt = 0; nt < 8; nt++)
                    mma_tf32(acc[mt][nt], af[mt], bf[nt]);
        }
        s ^= 1;
    }

#pragma unroll
    for (int mt = 0; mt < 2; mt++) {
        int row0 = bm * 128 + wrow * 32 + mt * 16 + gid;
#pragma unroll
        for (int nt = 0; nt < 8; nt++) {
            int col = bn * 128 + wcol * 64 + nt * 8 + tig * 2;
            float2 bv = *(const float2*)(bias + col);
            float c0 = acc[mt][nt][0] + bv.x, c1 = acc[mt][nt][1] + bv.y;
            float c2 = acc[mt][nt][2] + bv.x, c3 = acc[mt][nt][3] + bv.y;
            if (MODE == 1) {
                int local = col % 192;           // uniform per nt-block
                if (local < 128) {
                    unsigned* C = (unsigned*)Cv;
                    *(uint2*)(C + (size_t)row0 * N + col) = make_uint2(f2tf32(c0), f2tf32(c1));
                    *(uint2*)(C + (size_t)(row0 + 8) * N + col) = make_uint2(f2tf32(c2), f2tf32(c3));
                } else {
                    int hh = col / 192, d = local - 128;
                    int bq = row0 >> 11, sq = row0 & 2047;
                    size_t vb = ((size_t)(bq * NHEADS + hh) * DH + d) * S_LEN + sq;
                    vt[vb]              = f2tf32(c0);
                    vt[vb + S_LEN]      = f2tf32(c1);
                    vt[vb + 8]          = f2tf32(c2);
                    vt[vb + S_LEN + 8]  = f2tf32(c3);
                }
            } else {
                float* C = (float*)Cv;
                *(float2*)(C + (size_t)row0 * N + col) = make_float2(c0, c1);
                *(float2*)(C + (size_t)(row0 + 8) * N + col) = make_float2(c2, c3);
            }
        }
    }
}

// ---------------------------------------------------------------------------
// Flash attention, tf32 tensor cores (causal, online softmax).
// BQ=128 (256 threads, 8 warps x 16 rows), BK=64; 2 CTAs/SM -> 16 warps/SM.
// K from qkv (seq-major), V from vt (d-major) -> all fragments via ldmatrix.
// ---------------------------------------------------------------------------
#define FKLD 68
#define KV_STAGE_WORDS (2 * 64 * FKLD)               // K tile + V tile = 8704
#define OFF_PS (2 * KV_STAGE_WORDS)
#define FLASH_SMEM_WORDS (2 * KV_STAGE_WORDS + 128 * FKLD) // 26112 (104448 B)

__global__ __launch_bounds__(256, 2)
void flash_mma_kernel(const unsigned* __restrict__ qkv, const unsigned* __restrict__ vt,
                      unsigned* __restrict__ attn) {
    extern __shared__ unsigned fsm[];
    unsigned* Ps = fsm + OFF_PS;

    const int qt = gridDim.x - 1 - blockIdx.x;   // heavy tiles first
    const int h = blockIdx.y, b = blockIdx.z;
    const int tid = threadIdx.x;
    const int warp = tid >> 5, lane = tid & 31;
    const int gid = lane >> 2, tig = lane & 3;
    const int q8 = lane >> 3, r8 = lane & 7;
    const int m0 = warp * 16;
    const int tokbase = b * S_LEN;
    const float scale = 0.125f;      // 1/sqrt(64)
    const int ktmax = 2 * qt + 1;

    const unsigned smem_base = (unsigned)__cvta_generic_to_shared(fsm);
    const unsigned* vtb = vt + (size_t)(b * NHEADS + h) * DH * S_LEN;

    auto issue_kv = [&](int s, int kt) {
        unsigned ks_b = smem_base + (unsigned)(s * KV_STAGE_WORDS) * 4u;
        unsigned vs_b = ks_b + 64u * FKLD * 4u;
#pragma unroll
        for (int c = 0; c < 4; c++) {
            int i = tid + c * 256;
            int row = i >> 4, c4 = (i & 15) << 2;
            cp_async16(ks_b + (unsigned)(row * FKLD + c4) * 4u,
                       qkv + (size_t)(tokbase + kt * 64 + row) * QKV_LD + h * 192 + 64 + c4);
            cp_async16(vs_b + (unsigned)(row * FKLD + c4) * 4u,
                       vtb + (size_t)row * S_LEN + kt * 64 + c4);
        }
        cp_commit();
    };

    // ldmatrix per-lane offsets (n-major pattern, stride FKLD)
    unsigned nmOff[4];
#pragma unroll
    for (int p = 0; p < 4; p++)
        nmOff[p] = (unsigned)(((p * 16 + r8 + (q8 >> 1) * 8) * FKLD + (q8 & 1) * 4) * 4);
    const unsigned pAddr = smem_base + (unsigned)OFF_PS * 4u
        + (unsigned)(((m0 + r8 + (q8 & 1) * 8) * FKLD + (q8 >> 1) * 4) * 4);

    // ---- Q fragments in registers (loop-invariant) ----
    unsigned qf[8][4];
    {
        const size_t r0 = (size_t)(tokbase + qt * 128 + m0 + gid) * QKV_LD + h * 192;
        const size_t r1 = r0 + 8 * QKV_LD;
#pragma unroll
        for (int ks = 0; ks < 8; ks++) {
            int col = ks * 8 + tig;
            qf[ks][0] = qkv[r0 + col];
            qf[ks][1] = qkv[r1 + col];
            qf[ks][2] = qkv[r0 + col + 4];
            qf[ks][3] = qkv[r1 + col + 4];
        }
    }

    issue_kv(0, 0);

    float o[8][4];
    float m[2], l[2];
#pragma unroll
    for (int nt = 0; nt < 8; nt++)
#pragma unroll
        for (int i = 0; i < 4; i++) o[nt][i] = 0.f;
    m[0] = m[1] = -INFINITY;
    l[0] = l[1] = 0.f;

    int s = 0;
    for (int kt = 0; kt <= ktmax; kt++) {
        cp_wait0();
        __syncthreads();              // stage s ready; prior reads of s^1 done
        if (kt < ktmax) issue_kv(s ^ 1, kt + 1);

        // final tile: warps covering local rows < 64 are fully masked -> skip
        if (!(kt == ktmax && m0 < 64)) {
            const unsigned kStage = smem_base + (unsigned)(s * KV_STAGE_WORDS) * 4u;
            const unsigned vStage = kStage + 64u * FKLD * 4u;

            // ---- S = Q K^T (B-frags via ldmatrix on Ks) ----
            float acc[8][4];
#pragma unroll
            for (int nt = 0; nt < 8; nt++)
#pragma unroll
                for (int i = 0; i < 4; i++) acc[nt][i] = 0.f;

#pragma unroll
            for (int ks = 0; ks < 8; ks++) {
                unsigned bf[8][2];
#pragma unroll
                for (int p = 0; p < 4; p++)
                    ldsm_x4(bf[2*p][0], bf[2*p][1], bf[2*p+1][0], bf[2*p+1][1],
                            kStage + nmOff[p] + ks * 32);
#pragma unroll
                for (int nt = 0; nt < 8; nt++)
                    mma_tf32(acc[nt], qf[ks], bf[nt]);
            }

            // ---- scale + causal mask (last two tiles only) ----
#pragma unroll
            for (int nt = 0; nt < 8; nt++)
#pragma unroll
                for (int i = 0; i < 4; i++) acc[nt][i] *= scale;
            if (kt >= 2 * qt) {
                const int i0 = qt * 128 + m0 + gid;
                const int i1 = i0 + 8;
#pragma unroll
                for (int nt = 0; nt < 8; nt++) {
                    int j0 = kt * 64 + nt * 8 + 2 * tig, j1 = j0 + 1;
                    if (j0 > i0) acc[nt][0] = -INFINITY;
                    if (j1 > i0) acc[nt][1] = -INFINITY;
                    if (j0 > i1) acc[nt][2] = -INFINITY;
                    if (j1 > i1) acc[nt][3] = -INFINITY;
                }
            }

            // ---- online softmax (row spread over 4 tig-lanes) ----
#pragma unroll
            for (int r = 0; r < 2; r++) {
                float mx = -INFINITY;
#pragma unroll
                for (int nt = 0; nt < 8; nt++)
                    mx = fmaxf(mx, fmaxf(acc[nt][2 * r], acc[nt][2 * r + 1]));
                mx = fmaxf(mx, __shfl_xor_sync(0xffffffffu, mx, 1));
                mx = fmaxf(mx, __shfl_xor_sync(0xffffffffu, mx, 2));
                float mn = fmaxf(m[r], mx);

                float ls = 0.f;
                const int prow = (m0 + gid + 8 * r) * FKLD;
#pragma unroll
                for (int nt = 0; nt < 8; nt++) {
                    float p0 = __expf(acc[nt][2 * r] - mn);
                    float p1 = __expf(acc[nt][2 * r + 1] - mn);
                    unsigned t0 = f2tf32(p0), t1 = f2tf32(p1);
                    ls += __uint_as_float(t0) + __uint_as_float(t1);
                    *(uint2*)(Ps + prow + nt * 8 + 2 * tig) = make_uint2(t0, t1);
                }
                ls += __shfl_xor_sync(0xffffffffu, ls, 1);
                ls += __shfl_xor_sync(0xffffffffu, ls, 2);

                float f = __expf(m[r] - mn);
                l[r] = l[r] * f + ls;
                m[r] = mn;
#pragma unroll
                for (int nt = 0; nt < 8; nt++) {
                    o[nt][2 * r] *= f;
                    o[nt][2 * r + 1] *= f;
                }
            }
            __syncwarp();   // warp-private Ps visible

            // ---- O += P @ V (A-frags from Ps, B-frags from Vt; all ldmatrix) ----
#pragma unroll
            for (int ks = 0; ks < 8; ks++) {
                unsigned a[4];
                ldsm_x4(a[0], a[1], a[2], a[3], pAddr + ks * 32);
                unsigned bf[8][2];
#pragma unroll
                for (int p = 0; p < 4; p++)
                    ldsm_x4(bf[2*p][0], bf[2*p][1], bf[2*p+1][0], bf[2*p+1][1],
                            vStage + nmOff[p] + ks * 32);
#pragma unroll
                for (int nt = 0; nt < 8; nt++)
                    mma_tf32(o[nt], a, bf[nt]);
            }
            __syncwarp();   // Ps reads done before next iter's overwrite
        }
        s ^= 1;
    }

    // ---- normalize + write tf32-rounded bits to [tok, h*64+d] ----
    const float inv0 = 1.0f / l[0], inv1 = 1.0f / l[1];
    const int row0 = tokbase + qt * 128 + m0 + gid;
#pragma unroll
    for (int nt = 0; nt < 8; nt++) {
        int col = h * DH + nt * 8 + 2 * tig;
        uint2 v0 = make_uint2(f2tf32(o[nt][0] * inv0), f2tf32(o[nt][1] * inv0));
        uint2 v1 = make_uint2(f2tf32(o[nt][2] * inv1), f2tf32(o[nt][3] * inv1));
        *(uint2*)(attn + (size_t)row0 * D_MODEL + col) = v0;
        *(uint2*)(attn + (size_t)(row0 + 8) * D_MODEL + col) = v1;
    }
}

// ---------------------------------------------------------------------------
// Launch
// ---------------------------------------------------------------------------
extern "C" void kernel_launch(void* const* d_in, const int* in_sizes, int n_in,
                              void* d_out, int out_size) {
    const float* x    = (const float*)d_in[0];   // [2,2048,1024]
    const float* Wqkv = (const float*)d_in[1];   // [1024,3072]
    const float* bqkv = (const float*)d_in[2];   // [3072]
    const float* Wout = (const float*)d_in[3];   // [1024,1024]
    const float* bout = (const float*)d_in[4];   // [1024]
    float* out = (float*)d_out;                  // [2,2048,1024]

    unsigned* qkv;   cudaGetSymbolAddress((void**)&qkv,   g_qkv);
    unsigned* vt;    cudaGetSymbolAddress((void**)&vt,    g_vt);
    unsigned* attn;  cudaGetSymbolAddress((void**)&attn,  g_attn);
    unsigned* xt;    cudaGetSymbolAddress((void**)&xt,    g_xt);
    unsigned* wqkvt; cudaGetSymbolAddress((void**)&wqkvt, g_wqkvt);
    unsigned* woutt; cudaGetSymbolAddress((void**)&woutt, g_woutt);

    cudaFuncSetAttribute(tf32_gemm_bias<1>, cudaFuncAttributeMaxDynamicSharedMemorySize,
                         GEMM_SMEM_BYTES);
    cudaFuncSetAttribute(tf32_gemm_bias<0>, cudaFuncAttributeMaxDynamicSharedMemorySize,
                         GEMM_SMEM_BYTES);
    const int flash_smem = FLASH_SMEM_WORDS * (int)sizeof(unsigned);  // 104448 B
    cudaFuncSetAttribute(flash_mma_kernel, cudaFuncAttributeMaxDynamicSharedMemorySize,
                         flash_smem);

    // 0) Pre-convert: x -> tf32 bits; weights -> tf32 bits TRANSPOSED
    {
        int n4 = NTOK * D_MODEL / 4;
        cvt_tf32_kernel<<<(n4 + 255) / 256, 256>>>((const float4*)x, (uint4*)xt, n4);
        dim3 g1(QKV_LD / 32, D_MODEL / 32);
        cvt_t_tf32_kernel<<<g1, 256>>>(Wqkv, wqkvt, D_MODEL, QKV_LD);
        dim3 g2(D_MODEL / 32, D_MODEL / 32);
        cvt_t_tf32_kernel<<<g2, 256>>>(Wout, woutt, D_MODEL, D_MODEL);
    }

    // 1) QKV projection -> q/k tf32 bits + V^T tf32 bits
    {
        dim3 grid(QKV_LD / 128, NTOK / 128);
        tf32_gemm_bias<1><<<grid, 256, GEMM_SMEM_BYTES>>>(xt, wqkvt, bqkv, qkv, vt,
                                                          NTOK, QKV_LD, D_MODEL);
    }

    // 2) Causal flash attention (BQ=128, 16 warps/SM, all-ldmatrix fragments)
    {
        dim3 grid(S_LEN / 128, NHEADS, 2);
        flash_mma_kernel<<<grid, 256, flash_smem>>>(qkv, vt, attn);
    }

    // 3) Output projection -> fp32 out
    {
        dim3 grid(D_MODEL / 128, NTOK / 128);
        tf32_gemm_bias<0><<<grid, 256, GEMM_SMEM_BYTES>>>(attn, woutt, bout, out, nullptr,
                                                          NTOK, D_MODEL, D_MODEL);
    }
}

// round 15
// speedup vs baseline: 1.0263x; 1.0263x over previous
#include <cuda_runtime.h>
#include <cmath>

// Problem constants
#define S_LEN    2048
#define D_MODEL  1024
#define NHEADS   16
#define DH       64
#define QKV_LD   3072   // 3*D
#define NTOK     4096   // B*S

// Scratch (module-static device globals)
__device__ unsigned g_qkv[(size_t)NTOK * QKV_LD];      // tf32 bits; V third unused
__device__ unsigned g_vt[(size_t)2 * NHEADS * DH * S_LEN]; // tf32 bits V^T [b,h,d,seq]
__device__ unsigned g_attn[(size_t)NTOK * D_MODEL];    // tf32-bit attention output
__device__ unsigned g_xt[(size_t)NTOK * D_MODEL];      // tf32-bit x
__device__ unsigned g_wqkvt[(size_t)D_MODEL * QKV_LD]; // tf32-bit Wqkv^T [3072][1024]
__device__ unsigned g_woutt[(size_t)D_MODEL * D_MODEL];// tf32-bit Wout^T [1024][1024]

// ---------------------------------------------------------------------------
// helpers
// ---------------------------------------------------------------------------
__device__ __forceinline__ unsigned f2tf32(float x) {
    unsigned u;
    asm("cvt.rna.tf32.f32 %0, %1;" : "=r"(u) : "f"(x));
    return u;
}

__device__ __forceinline__ void mma_tf32(float* c, const unsigned* a, const unsigned* b) {
    asm volatile(
        "mma.sync.aligned.m16n8k8.row.col.f32.tf32.tf32.f32 "
        "{%0,%1,%2,%3}, {%4,%5,%6,%7}, {%8,%9}, {%0,%1,%2,%3};"
        : "+f"(c[0]), "+f"(c[1]), "+f"(c[2]), "+f"(c[3])
        : "r"(a[0]), "r"(a[1]), "r"(a[2]), "r"(a[3]), "r"(b[0]), "r"(b[1]));
}

__device__ __forceinline__ void ldsm_x4(unsigned& r0, unsigned& r1, unsigned& r2,
                                        unsigned& r3, unsigned addr) {
    asm volatile("ldmatrix.sync.aligned.m8n8.x4.shared.b16 {%0,%1,%2,%3}, [%4];"
                 : "=r"(r0), "=r"(r1), "=r"(r2), "=r"(r3) : "r"(addr));
}

__device__ __forceinline__ void cp_async16(unsigned smem_addr, const void* gptr) {
    asm volatile("cp.async.cg.shared.global [%0], [%1], 16;"
                 :: "r"(smem_addr), "l"(gptr));
}
__device__ __forceinline__ void cp_commit() { asm volatile("cp.async.commit_group;"); }
__device__ __forceinline__ void cp_wait0()  { asm volatile("cp.async.wait_group 0;"); }

// ---------------------------------------------------------------------------
// Pre-pass kernels: tf32 convert (x) and tf32 convert + transpose (weights)
// ---------------------------------------------------------------------------
__global__ void cvt_tf32_kernel(const float4* __restrict__ src,
                                uint4* __restrict__ dst, int n4) {
    int i = blockIdx.x * blockDim.x + threadIdx.x;
    if (i < n4) {
        float4 v = src[i];
        dst[i] = make_uint4(f2tf32(v.x), f2tf32(v.y), f2tf32(v.z), f2tf32(v.w));
    }
}

// src [K][N] fp32 -> dst [N][K] tf32 bits; K,N multiples of 32; 256 threads
__global__ void cvt_t_tf32_kernel(const float* __restrict__ src,
                                  unsigned* __restrict__ dst, int K, int N) {
    __shared__ unsigned sm[32][33];
    const int tx = threadIdx.x & 31, ty = threadIdx.x >> 5;   // 32 x 8
    const int k0 = blockIdx.y * 32, n0 = blockIdx.x * 32;
#pragma unroll
    for (int i = 0; i < 4; i++) {
        int rr = ty + 8 * i;
        sm[tx][rr] = f2tf32(src[(size_t)(k0 + rr) * N + n0 + tx]);
    }
    __syncthreads();
#pragma unroll
    for (int i = 0; i < 4; i++) {
        int rr = ty + 8 * i;
        dst[(size_t)(n0 + rr) * K + k0 + tx] = sm[rr][tx];
    }
}

// ---------------------------------------------------------------------------
// tf32 tensor-core GEMM + bias; A [M][K] tf32 bits, B TRANSPOSED [N][K] tf32 bits.
// cp.async double-buffered; fragments via ldmatrix.x4. (validated R11)
// MODE 0: fp32 out. MODE 1: qkv writer — q/k thirds -> tf32 bits in C,
//         V third -> tf32 bits TRANSPOSED into vt[b,h,d,seq].
// ---------------------------------------------------------------------------
#define TS_W 36
#define BUF_WORDS (2 * 128 * TS_W)           // 9216 words per stage
#define GEMM_SMEM_BYTES (2 * BUF_WORDS * 4)  // 73728

template<int MODE>
__global__ __launch_bounds__(256, 2)
void tf32_gemm_bias(const unsigned* __restrict__ A, const unsigned* __restrict__ Bt,
                    const float* __restrict__ bias, void* __restrict__ Cv,
                    unsigned* __restrict__ vt,
                    int M, int N, int K) {
    extern __shared__ unsigned gsm[];

    const int tid  = threadIdx.x;
    const int warp = tid >> 5, lane = tid & 31;
    const int gid  = lane >> 2, tig = lane & 3;
    const int q8   = lane >> 3, r8 = lane & 7;
    const int wrow = warp >> 1, wcol = warp & 1;
    const int bm = blockIdx.y, bn = blockIdx.x;

    int lrow[4], lcol[4];
#pragma unroll
    for (int c = 0; c < 4; c++) {
        int idx4 = tid + c * 256;
        lrow[c] = idx4 >> 3;  lcol[c] = (idx4 & 7) * 4;
    }

    const unsigned smem_base = (unsigned)__cvta_generic_to_shared(gsm);

    auto issue_tile = [&](int s, int k0) {
        unsigned as_b = smem_base + (unsigned)(s * BUF_WORDS) * 4u;
        unsigned bs_b = as_b + 128u * TS_W * 4u;
#pragma unroll
        for (int c = 0; c < 4; c++) {
            cp_async16(as_b + (unsigned)(lrow[c] * TS_W + lcol[c]) * 4u,
                       A + (size_t)(bm * 128 + lrow[c]) * K + k0 + lcol[c]);
            cp_async16(bs_b + (unsigned)(lrow[c] * TS_W + lcol[c]) * 4u,
                       Bt + (size_t)(bn * 128 + lrow[c]) * K + k0 + lcol[c]);
        }
        cp_commit();
    };

    unsigned aOff[2], bOff[4];
#pragma unroll
    for (int mt = 0; mt < 2; mt++)
        aOff[mt] = (unsigned)(((wrow * 32 + mt * 16 + r8 + (q8 & 1) * 8) * TS_W
                              + (q8 >> 1) * 4) * 4);
#pragma unroll
    for (int p = 0; p < 4; p++)
        bOff[p] = (unsigned)((128 * TS_W
                              + (wcol * 64 + p * 16 + r8 + (q8 >> 1) * 8) * TS_W
                              + (q8 & 1) * 4) * 4);

    float acc[2][8][4];
#pragma unroll
    for (int mt = 0; mt < 2; mt++)
#pragma unroll
        for (int nt = 0; nt < 8; nt++)
#pragma unroll
            for (int i = 0; i < 4; i++) acc[mt][nt][i] = 0.f;

    issue_tile(0, 0);

    int s = 0;
    for (int k0 = 0; k0 < K; k0 += 32) {
        cp_wait0();
        __syncthreads();
        if (k0 + 32 < K) issue_tile(s ^ 1, k0 + 32);

        const unsigned stage = smem_base + (unsigned)(s * BUF_WORDS) * 4u;

#pragma unroll
        for (int ks = 0; ks < 4; ks++) {
            unsigned af[2][4];
            ldsm_x4(af[0][0], af[0][1], af[0][2], af[0][3], stage + aOff[0] + ks * 32);
            ldsm_x4(af[1][0], af[1][1], af[1][2], af[1][3], stage + aOff[1] + ks * 32);
            unsigned bf[8][2];
#pragma unroll
            for (int p = 0; p < 4; p++)
                ldsm_x4(bf[2*p][0], bf[2*p][1], bf[2*p+1][0], bf[2*p+1][1],
                        stage + bOff[p] + ks * 32);
#pragma unroll
            for (int mt = 0; mt < 2; mt++)
#pragma unroll
                for (int nt = 0; nt < 8; nt++)
                    mma_tf32(acc[mt][nt], af[mt], bf[nt]);
        }
        s ^= 1;
    }

#pragma unroll
    for (int mt = 0; mt < 2; mt++) {
        int row0 = bm * 128 + wrow * 32 + mt * 16 + gid;
#pragma unroll
        for (int nt = 0; nt < 8; nt++) {
            int col = bn * 128 + wcol * 64 + nt * 8 + tig * 2;
            float2 bv = *(const float2*)(bias + col);
            float c0 = acc[mt][nt][0] + bv.x, c1 = acc[mt][nt][1] + bv.y;
            float c2 = acc[mt][nt][2] + bv.x, c3 = acc[mt][nt][3] + bv.y;
            if (MODE == 1) {
                int local = col % 192;           // uniform per nt-block
                if (local < 128) {
                    unsigned* C = (unsigned*)Cv;
                    *(uint2*)(C + (size_t)row0 * N + col) = make_uint2(f2tf32(c0), f2tf32(c1));
                    *(uint2*)(C + (size_t)(row0 + 8) * N + col) = make_uint2(f2tf32(c2), f2tf32(c3));
                } else {
                    int hh = col / 192, d = local - 128;
                    int bq = row0 >> 11, sq = row0 & 2047;
                    size_t vb = ((size_t)(bq * NHEADS + hh) * DH + d) * S_LEN + sq;
                    vt[vb]              = f2tf32(c0);
                    vt[vb + S_LEN]      = f2tf32(c1);
                    vt[vb + 8]          = f2tf32(c2);
                    vt[vb + S_LEN + 8]  = f2tf32(c3);
                }
            } else {
                float* C = (float*)Cv;
                *(float2*)(C + (size_t)row0 * N + col) = make_float2(c0, c1);
                *(float2*)(C + (size_t)(row0 + 8) * N + col) = make_float2(c2, c3);
            }
        }
    }
}

// ---------------------------------------------------------------------------
// Flash attention, tf32 tensor cores (causal, online softmax).
// R11 shape: BQ=64, 128 threads (4 warps x 16 rows), 256-reg budget.
// K from qkv (seq-major), V from vt (d-major) -> ALL fragments via ldmatrix.
// ---------------------------------------------------------------------------
#define FKLD 68
#define KV_STAGE_WORDS (2 * 64 * FKLD)                 // K tile + V tile = 8704
#define OFF_PS (2 * KV_STAGE_WORDS)
#define FLASH_SMEM_WORDS (2 * KV_STAGE_WORDS + 64 * FKLD)  // 21760 (87040 B)

__global__ __launch_bounds__(128, 2)
void flash_mma_kernel(const unsigned* __restrict__ qkv, const unsigned* __restrict__ vt,
                      unsigned* __restrict__ attn) {
    extern __shared__ unsigned fsm[];
    unsigned* Ps = fsm + OFF_PS;

    const int qt = gridDim.x - 1 - blockIdx.x;   // heavy tiles first
    const int h = blockIdx.y, b = blockIdx.z;
    const int tid = threadIdx.x;
    const int warp = tid >> 5, lane = tid & 31;
    const int gid = lane >> 2, tig = lane & 3;
    const int q8 = lane >> 3, r8 = lane & 7;
    const int m0 = warp * 16;
    const int tokbase = b * S_LEN;
    const float scale = 0.125f;      // 1/sqrt(64)

    const unsigned smem_base = (unsigned)__cvta_generic_to_shared(fsm);
    const unsigned* vtb = vt + (size_t)(b * NHEADS + h) * DH * S_LEN;

    // cp.async coords: 64x64 tile, 1024 float4s, 8 per thread
    int krow[8], kc4[8];
#pragma unroll
    for (int c = 0; c < 8; c++) {
        int i = tid + c * 128;
        krow[c] = i >> 4;  kc4[c] = (i & 15) << 2;
    }

    auto issue_kv = [&](int s, int kt) {
        unsigned ks_b = smem_base + (unsigned)(s * KV_STAGE_WORDS) * 4u;
        unsigned vs_b = ks_b + 64u * FKLD * 4u;
#pragma unroll
        for (int c = 0; c < 8; c++) {
            int row = krow[c], c4 = kc4[c];
            cp_async16(ks_b + (unsigned)(row * FKLD + c4) * 4u,
                       qkv + (size_t)(tokbase + kt * 64 + row) * QKV_LD + h * 192 + 64 + c4);
            cp_async16(vs_b + (unsigned)(row * FKLD + c4) * 4u,
                       vtb + (size_t)row * S_LEN + kt * 64 + c4);
        }
        cp_commit();
    };

    // ldmatrix per-lane offsets (n-major pattern, stride FKLD)
    unsigned nmOff[4];
#pragma unroll
    for (int p = 0; p < 4; p++)
        nmOff[p] = (unsigned)(((p * 16 + r8 + (q8 >> 1) * 8) * FKLD + (q8 & 1) * 4) * 4);
    const unsigned pAddr = smem_base + (unsigned)OFF_PS * 4u
        + (unsigned)(((m0 + r8 + (q8 & 1) * 8) * FKLD + (q8 >> 1) * 4) * 4);

    // ---- Q fragments in registers (loop-invariant) ----
    unsigned qf[8][4];
    {
        const size_t r0 = (size_t)(tokbase + qt * 64 + m0 + gid) * QKV_LD + h * 192;
        const size_t r1 = r0 + 8 * QKV_LD;
#pragma unroll
        for (int ks = 0; ks < 8; ks++) {
            int col = ks * 8 + tig;
            qf[ks][0] = qkv[r0 + col];
            qf[ks][1] = qkv[r1 + col];
            qf[ks][2] = qkv[r0 + col + 4];
            qf[ks][3] = qkv[r1 + col + 4];
        }
    }

    issue_kv(0, 0);

    float o[8][4];
    float m[2], l[2];
#pragma unroll
    for (int nt = 0; nt < 8; nt++)
#pragma unroll
        for (int i = 0; i < 4; i++) o[nt][i] = 0.f;
    m[0] = m[1] = -INFINITY;
    l[0] = l[1] = 0.f;

    int s = 0;
    for (int kt = 0; kt <= qt; kt++) {
        cp_wait0();
        __syncthreads();              // stage s ready; prior reads of s^1 done
        if (kt < qt) issue_kv(s ^ 1, kt + 1);

        const unsigned kStage = smem_base + (unsigned)(s * KV_STAGE_WORDS) * 4u;
        const unsigned vStage = kStage + 64u * FKLD * 4u;

        // ---- S = Q K^T (B-frags via ldmatrix on Ks) ----
        float acc[8][4];
#pragma unroll
        for (int nt = 0; nt < 8; nt++)
#pragma unroll
            for (int i = 0; i < 4; i++) acc[nt][i] = 0.f;

#pragma unroll
        for (int ks = 0; ks < 8; ks++) {
            unsigned bf[8][2];
#pragma unroll
            for (int p = 0; p < 4; p++)
                ldsm_x4(bf[2*p][0], bf[2*p][1], bf[2*p+1][0], bf[2*p+1][1],
                        kStage + nmOff[p] + ks * 32);
#pragma unroll
            for (int nt = 0; nt < 8; nt++)
                mma_tf32(acc[nt], qf[ks], bf[nt]);
        }

        // ---- scale + causal mask (diag tile only) ----
        const bool diag = (kt == qt);
#pragma unroll
        for (int nt = 0; nt < 8; nt++)
#pragma unroll
            for (int i = 0; i < 4; i++) acc[nt][i] *= scale;
        if (diag) {
            const int i0 = m0 + gid;
            const int i1 = m0 + gid + 8;
#pragma unroll
            for (int nt = 0; nt < 8; nt++) {
                int j0 = nt * 8 + 2 * tig, j1 = j0 + 1;
                if (j0 > i0) acc[nt][0] = -INFINITY;
                if (j1 > i0) acc[nt][1] = -INFINITY;
                if (j0 > i1) acc[nt][2] = -INFINITY;
                if (j1 > i1) acc[nt][3] = -INFINITY;
            }
        }

        // ---- online softmax (row spread over 4 tig-lanes) ----
#pragma unroll
        for (int r = 0; r < 2; r++) {
            float mx = -INFINITY;
#pragma unroll
            for (int nt = 0; nt < 8; nt++)
                mx = fmaxf(mx, fmaxf(acc[nt][2 * r], acc[nt][2 * r + 1]));
            mx = fmaxf(mx, __shfl_xor_sync(0xffffffffu, mx, 1));
            mx = fmaxf(mx, __shfl_xor_sync(0xffffffffu, mx, 2));
            float mn = fmaxf(m[r], mx);

            float ls = 0.f;
            const int prow = (m0 + gid + 8 * r) * FKLD;
#pragma unroll
            for (int nt = 0; nt < 8; nt++) {
                float p0 = __expf(acc[nt][2 * r] - mn);
                float p1 = __expf(acc[nt][2 * r + 1] - mn);
                unsigned t0 = f2tf32(p0), t1 = f2tf32(p1);
                ls += __uint_as_float(t0) + __uint_as_float(t1);
                *(uint2*)(Ps + prow + nt * 8 + 2 * tig) = make_uint2(t0, t1);
            }
            ls += __shfl_xor_sync(0xffffffffu, ls, 1);
            ls += __shfl_xor_sync(0xffffffffu, ls, 2);

            float f = __expf(m[r] - mn);
            l[r] = l[r] * f + ls;
            m[r] = mn;
#pragma unroll
            for (int nt = 0; nt < 8; nt++) {
                o[nt][2 * r] *= f;
                o[nt][2 * r + 1] *= f;
            }
        }
        __syncwarp();   // warp-private Ps visible

        // ---- O += P @ V (A-frags from Ps, B-frags from Vt; all ldmatrix) ----
#pragma unroll
        for (int ks = 0; ks < 8; ks++) {
            unsigned a[4];
            ldsm_x4(a[0], a[1], a[2], a[3], pAddr + ks * 32);
            unsigned bf[8][2];
#pragma unroll
            for (int p = 0; p < 4; p++)
                ldsm_x4(bf[2*p][0], bf[2*p][1], bf[2*p+1][0], bf[2*p+1][1],
                        vStage + nmOff[p] + ks * 32);
#pragma unroll
            for (int nt = 0; nt < 8; nt++)
                mma_tf32(o[nt], a, bf[nt]);
        }
        __syncwarp();   // Ps reads done before next iter's overwrite
        s ^= 1;
    }

    // ---- normalize + write tf32-rounded bits to [tok, h*64+d] ----
    const float inv0 = 1.0f / l[0], inv1 = 1.0f / l[1];
    const int row0 = tokbase + qt * 64 + m0 + gid;
#pragma unroll
    for (int nt = 0; nt < 8; nt++) {
        int col = h * DH + nt * 8 + 2 * tig;
        uint2 v0 = make_uint2(f2tf32(o[nt][0] * inv0), f2tf32(o[nt][1] * inv0));
        uint2 v1 = make_uint2(f2tf32(o[nt][2] * inv1), f2tf32(o[nt][3] * inv1));
        *(uint2*)(attn + (size_t)row0 * D_MODEL + col) = v0;
        *(uint2*)(attn + (size_t)(row0 + 8) * D_MODEL + col) = v1;
    }
}

// ---------------------------------------------------------------------------
// Launch
// ---------------------------------------------------------------------------
extern "C" void kernel_launch(void* const* d_in, const int* in_sizes, int n_in,
                              void* d_out, int out_size) {
    const float* x    = (const float*)d_in[0];   // [2,2048,1024]
    const float* Wqkv = (const float*)d_in[1];   // [1024,3072]
    const float* bqkv = (const float*)d_in[2];   // [3072]
    const float* Wout = (const float*)d_in[3];   // [1024,1024]
    const float* bout = (const float*)d_in[4];   // [1024]
    float* out = (float*)d_out;                  // [2,2048,1024]

    unsigned* qkv;   cudaGetSymbolAddress((void**)&qkv,   g_qkv);
    unsigned* vt;    cudaGetSymbolAddress((void**)&vt,    g_vt);
    unsigned* attn;  cudaGetSymbolAddress((void**)&attn,  g_attn);
    unsigned* xt;    cudaGetSymbolAddress((void**)&xt,    g_xt);
    unsigned* wqkvt; cudaGetSymbolAddress((void**)&wqkvt, g_wqkvt);
    unsigned* woutt; cudaGetSymbolAddress((void**)&woutt, g_woutt);

    cudaFuncSetAttribute(tf32_gemm_bias<1>, cudaFuncAttributeMaxDynamicSharedMemorySize,
                         GEMM_SMEM_BYTES);
    cudaFuncSetAttribute(tf32_gemm_bias<0>, cudaFuncAttributeMaxDynamicSharedMemorySize,
                         GEMM_SMEM_BYTES);
    const int flash_smem = FLASH_SMEM_WORDS * (int)sizeof(unsigned);  // 87040 B
    cudaFuncSetAttribute(flash_mma_kernel, cudaFuncAttributeMaxDynamicSharedMemorySize,
                         flash_smem);

    // 0) Pre-convert: x -> tf32 bits; weights -> tf32 bits TRANSPOSED
    {
        int n4 = NTOK * D_MODEL / 4;
        cvt_tf32_kernel<<<(n4 + 255) / 256, 256>>>((const float4*)x, (uint4*)xt, n4);
        dim3 g1(QKV_LD / 32, D_MODEL / 32);
        cvt_t_tf32_kernel<<<g1, 256>>>(Wqkv, wqkvt, D_MODEL, QKV_LD);
        dim3 g2(D_MODEL / 32, D_MODEL / 32);
        cvt_t_tf32_kernel<<<g2, 256>>>(Wout, woutt, D_MODEL, D_MODEL);
    }

    // 1) QKV projection -> q/k tf32 bits + V^T tf32 bits
    {
        dim3 grid(QKV_LD / 128, NTOK / 128);
        tf32_gemm_bias<1><<<grid, 256, GEMM_SMEM_BYTES>>>(xt, wqkvt, bqkv, qkv, vt,
                                                          NTOK, QKV_LD, D_MODEL);
    }

    // 2) Causal flash attention (BQ=64, 128 threads, all-ldmatrix fragments)
    {
        dim3 grid(S_LEN / 64, NHEADS, 2);
        flash_mma_kernel<<<grid, 128, flash_smem>>>(qkv, vt, attn);
    }

    // 3) Output projection -> fp32 out
    {
        dim3 grid(D_MODEL / 128, NTOK / 128);
        tf32_gemm_bias<0><<<grid, 256, GEMM_SMEM_BYTES>>>(attn, woutt, bout, out, nullptr,
                                                          NTOK, D_MODEL, D_MODEL);
    }
}

// round 16
// speedup vs baseline: 1.0409x; 1.0142x over previous
#include <cuda_runtime.h>
#include <cmath>

// Problem constants
#define S_LEN    2048
#define D_MODEL  1024
#define NHEADS   16
#define DH       64
#define QKV_LD   3072   // 3*D
#define NTOK     4096   // B*S

// Scratch (module-static device globals)
__device__ unsigned g_qkv[(size_t)NTOK * QKV_LD];      // tf32 bits; V third unused
__device__ unsigned g_vt[(size_t)2 * NHEADS * DH * S_LEN]; // tf32 bits V^T [b,h,d,seq]
__device__ unsigned g_attn[(size_t)NTOK * D_MODEL];    // tf32-bit attention output
__device__ unsigned g_xt[(size_t)NTOK * D_MODEL];      // tf32-bit x
__device__ unsigned g_wqkvt[(size_t)D_MODEL * QKV_LD]; // tf32-bit Wqkv^T [3072][1024]
__device__ unsigned g_woutt[(size_t)D_MODEL * D_MODEL];// tf32-bit Wout^T [1024][1024]

// ---------------------------------------------------------------------------
// helpers
// ---------------------------------------------------------------------------
__device__ __forceinline__ unsigned f2tf32(float x) {
    unsigned u;
    asm("cvt.rna.tf32.f32 %0, %1;" : "=r"(u) : "f"(x));
    return u;
}

__device__ __forceinline__ void mma_tf32(float* c, const unsigned* a, const unsigned* b) {
    asm volatile(
        "mma.sync.aligned.m16n8k8.row.col.f32.tf32.tf32.f32 "
        "{%0,%1,%2,%3}, {%4,%5,%6,%7}, {%8,%9}, {%0,%1,%2,%3};"
        : "+f"(c[0]), "+f"(c[1]), "+f"(c[2]), "+f"(c[3])
        : "r"(a[0]), "r"(a[1]), "r"(a[2]), "r"(a[3]), "r"(b[0]), "r"(b[1]));
}

__device__ __forceinline__ void ldsm_x4(unsigned& r0, unsigned& r1, unsigned& r2,
                                        unsigned& r3, unsigned addr) {
    asm volatile("ldmatrix.sync.aligned.m8n8.x4.shared.b16 {%0,%1,%2,%3}, [%4];"
                 : "=r"(r0), "=r"(r1), "=r"(r2), "=r"(r3) : "r"(addr));
}

__device__ __forceinline__ void cp_async16(unsigned smem_addr, const void* gptr) {
    asm volatile("cp.async.cg.shared.global [%0], [%1], 16;"
                 :: "r"(smem_addr), "l"(gptr));
}
__device__ __forceinline__ void cp_commit() { asm volatile("cp.async.commit_group;"); }
__device__ __forceinline__ void cp_wait0()  { asm volatile("cp.async.wait_group 0;"); }

// ---------------------------------------------------------------------------
// Pre-pass kernels: tf32 convert (x) and tf32 convert + transpose (weights)
// ---------------------------------------------------------------------------
__global__ void cvt_tf32_kernel(const float4* __restrict__ src,
                                uint4* __restrict__ dst, int n4) {
    int i = blockIdx.x * blockDim.x + threadIdx.x;
    if (i < n4) {
        float4 v = src[i];
        dst[i] = make_uint4(f2tf32(v.x), f2tf32(v.y), f2tf32(v.z), f2tf32(v.w));
    }
}

// src [K][N] fp32 -> dst [N][K] tf32 bits; K,N multiples of 32; 256 threads
__global__ void cvt_t_tf32_kernel(const float* __restrict__ src,
                                  unsigned* __restrict__ dst, int K, int N) {
    __shared__ unsigned sm[32][33];
    const int tx = threadIdx.x & 31, ty = threadIdx.x >> 5;   // 32 x 8
    const int k0 = blockIdx.y * 32, n0 = blockIdx.x * 32;
#pragma unroll
    for (int i = 0; i < 4; i++) {
        int rr = ty + 8 * i;
        sm[tx][rr] = f2tf32(src[(size_t)(k0 + rr) * N + n0 + tx]);
    }
    __syncthreads();
#pragma unroll
    for (int i = 0; i < 4; i++) {
        int rr = ty + 8 * i;
        dst[(size_t)(n0 + rr) * K + k0 + tx] = sm[rr][tx];
    }
}

// ---------------------------------------------------------------------------
// tf32 tensor-core GEMM + bias; A [M][K] tf32 bits, B TRANSPOSED [N][K] tf32 bits.
// cp.async double-buffered; fragments via ldmatrix.x4. (validated R11)
// MODE 0: fp32 out. MODE 1: qkv writer — q/k thirds -> tf32 bits in C,
//         V third -> tf32 bits TRANSPOSED into vt[b,h,d,seq].
// ---------------------------------------------------------------------------
#define TS_W 36
#define BUF_WORDS (2 * 128 * TS_W)           // 9216 words per stage
#define GEMM_SMEM_BYTES (2 * BUF_WORDS * 4)  // 73728

template<int MODE>
__global__ __launch_bounds__(256, 2)
void tf32_gemm_bias(const unsigned* __restrict__ A, const unsigned* __restrict__ Bt,
                    const float* __restrict__ bias, void* __restrict__ Cv,
                    unsigned* __restrict__ vt,
                    int M, int N, int K) {
    extern __shared__ unsigned gsm[];

    const int tid  = threadIdx.x;
    const int warp = tid >> 5, lane = tid & 31;
    const int gid  = lane >> 2, tig = lane & 3;
    const int q8   = lane >> 3, r8 = lane & 7;
    const int wrow = warp >> 1, wcol = warp & 1;
    const int bm = blockIdx.y, bn = blockIdx.x;

    int lrow[4], lcol[4];
#pragma unroll
    for (int c = 0; c < 4; c++) {
        int idx4 = tid + c * 256;
        lrow[c] = idx4 >> 3;  lcol[c] = (idx4 & 7) * 4;
    }

    const unsigned smem_base = (unsigned)__cvta_generic_to_shared(gsm);

    auto issue_tile = [&](int s, int k0) {
        unsigned as_b = smem_base + (unsigned)(s * BUF_WORDS) * 4u;
        unsigned bs_b = as_b + 128u * TS_W * 4u;
#pragma unroll
        for (int c = 0; c < 4; c++) {
            cp_async16(as_b + (unsigned)(lrow[c] * TS_W + lcol[c]) * 4u,
                       A + (size_t)(bm * 128 + lrow[c]) * K + k0 + lcol[c]);
            cp_async16(bs_b + (unsigned)(lrow[c] * TS_W + lcol[c]) * 4u,
                       Bt + (size_t)(bn * 128 + lrow[c]) * K + k0 + lcol[c]);
        }
        cp_commit();
    };

    unsigned aOff[2], bOff[4];
#pragma unroll
    for (int mt = 0; mt < 2; mt++)
        aOff[mt] = (unsigned)(((wrow * 32 + mt * 16 + r8 + (q8 & 1) * 8) * TS_W
                              + (q8 >> 1) * 4) * 4);
#pragma unroll
    for (int p = 0; p < 4; p++)
        bOff[p] = (unsigned)((128 * TS_W
                              + (wcol * 64 + p * 16 + r8 + (q8 >> 1) * 8) * TS_W
                              + (q8 & 1) * 4) * 4);

    float acc[2][8][4];
#pragma unroll
    for (int mt = 0; mt < 2; mt++)
#pragma unroll
        for (int nt = 0; nt < 8; nt++)
#pragma unroll
            for (int i = 0; i < 4; i++) acc[mt][nt][i] = 0.f;

    issue_tile(0, 0);

    int s = 0;
    for (int k0 = 0; k0 < K; k0 += 32) {
        cp_wait0();
        __syncthreads();
        if (k0 + 32 < K) issue_tile(s ^ 1, k0 + 32);

        const unsigned stage = smem_base + (unsigned)(s * BUF_WORDS) * 4u;

#pragma unroll
        for (int ks = 0; ks < 4; ks++) {
            unsigned af[2][4];
            ldsm_x4(af[0][0], af[0][1], af[0][2], af[0][3], stage + aOff[0] + ks * 32);
            ldsm_x4(af[1][0], af[1][1], af[1][2], af[1][3], stage + aOff[1] + ks * 32);
            unsigned bf[8][2];
#pragma unroll
            for (int p = 0; p < 4; p++)
                ldsm_x4(bf[2*p][0], bf[2*p][1], bf[2*p+1][0], bf[2*p+1][1],
                        stage + bOff[p] + ks * 32);
#pragma unroll
            for (int mt = 0; mt < 2; mt++)
#pragma unroll
                for (int nt = 0; nt < 8; nt++)
                    mma_tf32(acc[mt][nt], af[mt], bf[nt]);
        }
        s ^= 1;
    }

#pragma unroll
    for (int mt = 0; mt < 2; mt++) {
        int row0 = bm * 128 + wrow * 32 + mt * 16 + gid;
#pragma unroll
        for (int nt = 0; nt < 8; nt++) {
            int col = bn * 128 + wcol * 64 + nt * 8 + tig * 2;
            float2 bv = *(const float2*)(bias + col);
            float c0 = acc[mt][nt][0] + bv.x, c1 = acc[mt][nt][1] + bv.y;
            float c2 = acc[mt][nt][2] + bv.x, c3 = acc[mt][nt][3] + bv.y;
            if (MODE == 1) {
                int local = col % 192;           // uniform per nt-block
                if (local < 128) {
                    unsigned* C = (unsigned*)Cv;
                    *(uint2*)(C + (size_t)row0 * N + col) = make_uint2(f2tf32(c0), f2tf32(c1));
                    *(uint2*)(C + (size_t)(row0 + 8) * N + col) = make_uint2(f2tf32(c2), f2tf32(c3));
                } else {
                    int hh = col / 192, d = local - 128;
                    int bq = row0 >> 11, sq = row0 & 2047;
                    size_t vb = ((size_t)(bq * NHEADS + hh) * DH + d) * S_LEN + sq;
                    vt[vb]              = f2tf32(c0);
                    vt[vb + S_LEN]      = f2tf32(c1);
                    vt[vb + 8]          = f2tf32(c2);
                    vt[vb + S_LEN + 8]  = f2tf32(c3);
                }
            } else {
                float* C = (float*)Cv;
                *(float2*)(C + (size_t)row0 * N + col) = make_float2(c0, c1);
                *(float2*)(C + (size_t)(row0 + 8) * N + col) = make_float2(c2, c3);
            }
        }
    }
}

// ---------------------------------------------------------------------------
// Flash attention, tf32 tensor cores (causal, online softmax).
// BQ=64, 128 threads (4 warps x 16 rows). NO Ps smem: the S->P fragment
// permutation is done with warp shuffles (tig-lane permutation within each
// gid group), so smem = 2 KV stages only -> 69.6 KB -> 3 CTAs/SM (12 warps).
// K from qkv (seq-major), V from vt (d-major), both via ldmatrix.
// ---------------------------------------------------------------------------
#define FKLD 68
#define KV_STAGE_WORDS (2 * 64 * FKLD)                 // K tile + V tile = 8704
#define FLASH_SMEM_WORDS (2 * KV_STAGE_WORDS)          // 17408 (69632 B)

__global__ __launch_bounds__(128, 3)
void flash_mma_kernel(const unsigned* __restrict__ qkv, const unsigned* __restrict__ vt,
                      unsigned* __restrict__ attn) {
    extern __shared__ unsigned fsm[];

    const int qt = gridDim.x - 1 - blockIdx.x;   // heavy tiles first
    const int h = blockIdx.y, b = blockIdx.z;
    const int tid = threadIdx.x;
    const int warp = tid >> 5, lane = tid & 31;
    const int gid = lane >> 2, tig = lane & 3;
    const int q8 = lane >> 3, r8 = lane & 7;
    const int m0 = warp * 16;
    const int tokbase = b * S_LEN;
    const float scale = 0.125f;      // 1/sqrt(64)

    const unsigned smem_base = (unsigned)__cvta_generic_to_shared(fsm);
    const unsigned* vtb = vt + (size_t)(b * NHEADS + h) * DH * S_LEN;

    // shuffle sources for the S->P fragment permutation (fixed per lane)
    const int s0 = (lane & 28) | (tig >> 1);   // owner of col tig in this gid group
    const int s1 = s0 + 2;                     // owner of col tig+4
    const bool odd = (tig & 1);

    // cp.async coords: 64x64 tile, 1024 float4s, 8 per thread
    int krow[8], kc4[8];
#pragma unroll
    for (int c = 0; c < 8; c++) {
        int i = tid + c * 128;
        krow[c] = i >> 4;  kc4[c] = (i & 15) << 2;
    }

    auto issue_kv = [&](int s, int kt) {
        unsigned ks_b = smem_base + (unsigned)(s * KV_STAGE_WORDS) * 4u;
        unsigned vs_b = ks_b + 64u * FKLD * 4u;
#pragma unroll
        for (int c = 0; c < 8; c++) {
            int row = krow[c], c4 = kc4[c];
            cp_async16(ks_b + (unsigned)(row * FKLD + c4) * 4u,
                       qkv + (size_t)(tokbase + kt * 64 + row) * QKV_LD + h * 192 + 64 + c4);
            cp_async16(vs_b + (unsigned)(row * FKLD + c4) * 4u,
                       vtb + (size_t)row * S_LEN + kt * 64 + c4);
        }
        cp_commit();
    };

    // ldmatrix per-lane offsets (n-major pattern, stride FKLD)
    unsigned nmOff[4];
#pragma unroll
    for (int p = 0; p < 4; p++)
        nmOff[p] = (unsigned)(((p * 16 + r8 + (q8 >> 1) * 8) * FKLD + (q8 & 1) * 4) * 4);

    // ---- Q fragments in registers (loop-invariant) ----
    unsigned qf[8][4];
    {
        const size_t r0 = (size_t)(tokbase + qt * 64 + m0 + gid) * QKV_LD + h * 192;
        const size_t r1 = r0 + 8 * QKV_LD;
#pragma unroll
        for (int ks = 0; ks < 8; ks++) {
            int col = ks * 8 + tig;
            qf[ks][0] = qkv[r0 + col];
            qf[ks][1] = qkv[r1 + col];
            qf[ks][2] = qkv[r0 + col + 4];
            qf[ks][3] = qkv[r1 + col + 4];
        }
    }

    issue_kv(0, 0);

    float o[8][4];
    float m[2], l[2];
#pragma unroll
    for (int nt = 0; nt < 8; nt++)
#pragma unroll
        for (int i = 0; i < 4; i++) o[nt][i] = 0.f;
    m[0] = m[1] = -INFINITY;
    l[0] = l[1] = 0.f;

    int s = 0;
    for (int kt = 0; kt <= qt; kt++) {
        cp_wait0();
        __syncthreads();              // stage s ready; prior reads of s^1 done
        if (kt < qt) issue_kv(s ^ 1, kt + 1);

        const unsigned kStage = smem_base + (unsigned)(s * KV_STAGE_WORDS) * 4u;
        const unsigned vStage = kStage + 64u * FKLD * 4u;

        // ---- S = Q K^T (B-frags via ldmatrix on Ks) ----
        float acc[8][4];
#pragma unroll
        for (int nt = 0; nt < 8; nt++)
#pragma unroll
            for (int i = 0; i < 4; i++) acc[nt][i] = 0.f;

#pragma unroll
        for (int ks = 0; ks < 8; ks++) {
            unsigned bf[8][2];
#pragma unroll
            for (int p = 0; p < 4; p++)
                ldsm_x4(bf[2*p][0], bf[2*p][1], bf[2*p+1][0], bf[2*p+1][1],
                        kStage + nmOff[p] + ks * 32);
#pragma unroll
            for (int nt = 0; nt < 8; nt++)
                mma_tf32(acc[nt], qf[ks], bf[nt]);
        }

        // ---- scale + causal mask (diag tile only) ----
        const bool diag = (kt == qt);
#pragma unroll
        for (int nt = 0; nt < 8; nt++)
#pragma unroll
            for (int i = 0; i < 4; i++) acc[nt][i] *= scale;
        if (diag) {
            const int i0 = m0 + gid;
            const int i1 = m0 + gid + 8;
#pragma unroll
            for (int nt = 0; nt < 8; nt++) {
                int j0 = nt * 8 + 2 * tig, j1 = j0 + 1;
                if (j0 > i0) acc[nt][0] = -INFINITY;
                if (j1 > i0) acc[nt][1] = -INFINITY;
                if (j0 > i1) acc[nt][2] = -INFINITY;
                if (j1 > i1) acc[nt][3] = -INFINITY;
            }
        }

        // ---- online softmax; acc is overwritten with tf32-rounded P ----
#pragma unroll
        for (int r = 0; r < 2; r++) {
            float mx = -INFINITY;
#pragma unroll
            for (int nt = 0; nt < 8; nt++)
                mx = fmaxf(mx, fmaxf(acc[nt][2 * r], acc[nt][2 * r + 1]));
            mx = fmaxf(mx, __shfl_xor_sync(0xffffffffu, mx, 1));
            mx = fmaxf(mx, __shfl_xor_sync(0xffffffffu, mx, 2));
            float mn = fmaxf(m[r], mx);

            float ls = 0.f;
#pragma unroll
            for (int nt = 0; nt < 8; nt++) {
                float p0 = __expf(acc[nt][2 * r] - mn);
                float p1 = __expf(acc[nt][2 * r + 1] - mn);
                unsigned t0 = f2tf32(p0), t1 = f2tf32(p1);
                float f0 = __uint_as_float(t0), f1 = __uint_as_float(t1);
                ls += f0 + f1;
                acc[nt][2 * r]     = f0;      // P in C-fragment layout
                acc[nt][2 * r + 1] = f1;
            }
            ls += __shfl_xor_sync(0xffffffffu, ls, 1);
            ls += __shfl_xor_sync(0xffffffffu, ls, 2);

            float f = __expf(m[r] - mn);
            l[r] = l[r] * f + ls;
            m[r] = mn;
#pragma unroll
            for (int nt = 0; nt < 8; nt++) {
                o[nt][2 * r] *= f;
                o[nt][2 * r + 1] *= f;
            }
        }

        // ---- O += P @ V (A-frags via shuffle permutation; B-frags ldmatrix) ----
#pragma unroll
        for (int ks = 0; ks < 8; ks++) {
            float e0 = __shfl_sync(0xffffffffu, acc[ks][0], s0);
            float o0 = __shfl_sync(0xffffffffu, acc[ks][1], s0);
            float e1 = __shfl_sync(0xffffffffu, acc[ks][2], s0);
            float o1 = __shfl_sync(0xffffffffu, acc[ks][3], s0);
            float e2 = __shfl_sync(0xffffffffu, acc[ks][0], s1);
            float o2 = __shfl_sync(0xffffffffu, acc[ks][1], s1);
            float e3 = __shfl_sync(0xffffffffu, acc[ks][2], s1);
            float o3 = __shfl_sync(0xffffffffu, acc[ks][3], s1);
            unsigned a[4];
            a[0] = __float_as_uint(odd ? o0 : e0);
            a[1] = __float_as_uint(odd ? o1 : e1);
            a[2] = __float_as_uint(odd ? o2 : e2);
            a[3] = __float_as_uint(odd ? o3 : e3);
            unsigned bf[8][2];
#pragma unroll
            for (int p = 0; p < 4; p++)
                ldsm_x4(bf[2*p][0], bf[2*p][1], bf[2*p+1][0], bf[2*p+1][1],
                        vStage + nmOff[p] + ks * 32);
#pragma unroll
            for (int nt = 0; nt < 8; nt++)
                mma_tf32(o[nt], a, bf[nt]);
        }
        s ^= 1;
    }

    // ---- normalize + write tf32-rounded bits to [tok, h*64+d] ----
    const float inv0 = 1.0f / l[0], inv1 = 1.0f / l[1];
    const int row0 = tokbase + qt * 64 + m0 + gid;
#pragma unroll
    for (int nt = 0; nt < 8; nt++) {
        int col = h * DH + nt * 8 + 2 * tig;
        uint2 v0 = make_uint2(f2tf32(o[nt][0] * inv0), f2tf32(o[nt][1] * inv0));
        uint2 v1 = make_uint2(f2tf32(o[nt][2] * inv1), f2tf32(o[nt][3] * inv1));
        *(uint2*)(attn + (size_t)row0 * D_MODEL + col) = v0;
        *(uint2*)(attn + (size_t)(row0 + 8) * D_MODEL + col) = v1;
    }
}

// ---------------------------------------------------------------------------
// Launch
// ---------------------------------------------------------------------------
extern "C" void kernel_launch(void* const* d_in, const int* in_sizes, int n_in,
                              void* d_out, int out_size) {
    const float* x    = (const float*)d_in[0];   // [2,2048,1024]
    const float* Wqkv = (const float*)d_in[1];   // [1024,3072]
    const float* bqkv = (const float*)d_in[2];   // [3072]
    const float* Wout = (const float*)d_in[3];   // [1024,1024]
    const float* bout = (const float*)d_in[4];   // [1024]
    float* out = (float*)d_out;                  // [2,2048,1024]

    unsigned* qkv;   cudaGetSymbolAddress((void**)&qkv,   g_qkv);
    unsigned* vt;    cudaGetSymbolAddress((void**)&vt,    g_vt);
    unsigned* attn;  cudaGetSymbolAddress((void**)&attn,  g_attn);
    unsigned* xt;    cudaGetSymbolAddress((void**)&xt,    g_xt);
    unsigned* wqkvt; cudaGetSymbolAddress((void**)&wqkvt, g_wqkvt);
    unsigned* woutt; cudaGetSymbolAddress((void**)&woutt, g_woutt);

    cudaFuncSetAttribute(tf32_gemm_bias<1>, cudaFuncAttributeMaxDynamicSharedMemorySize,
                         GEMM_SMEM_BYTES);
    cudaFuncSetAttribute(tf32_gemm_bias<0>, cudaFuncAttributeMaxDynamicSharedMemorySize,
                         GEMM_SMEM_BYTES);
    const int flash_smem = FLASH_SMEM_WORDS * (int)sizeof(unsigned);  // 69632 B
    cudaFuncSetAttribute(flash_mma_kernel, cudaFuncAttributeMaxDynamicSharedMemorySize,
                         flash_smem);

    // 0) Pre-convert: x -> tf32 bits; weights -> tf32 bits TRANSPOSED
    {
        int n4 = NTOK * D_MODEL / 4;
        cvt_tf32_kernel<<<(n4 + 255) / 256, 256>>>((const float4*)x, (uint4*)xt, n4);
        dim3 g1(QKV_LD / 32, D_MODEL / 32);
        cvt_t_tf32_kernel<<<g1, 256>>>(Wqkv, wqkvt, D_MODEL, QKV_LD);
        dim3 g2(D_MODEL / 32, D_MODEL / 32);
        cvt_t_tf32_kernel<<<g2, 256>>>(Wout, woutt, D_MODEL, D_MODEL);
    }

    // 1) QKV projection -> q/k tf32 bits + V^T tf32 bits
    {
        dim3 grid(QKV_LD / 128, NTOK / 128);
        tf32_gemm_bias<1><<<grid, 256, GEMM_SMEM_BYTES>>>(xt, wqkvt, bqkv, qkv, vt,
                                                          NTOK, QKV_LD, D_MODEL);
    }

    // 2) Causal flash attention (BQ=64, 3 CTAs/SM, shuffle P-permutation)
    {
        dim3 grid(S_LEN / 64, NHEADS, 2);
        flash_mma_kernel<<<grid, 128, flash_smem>>>(qkv, vt, attn);
    }

    // 3) Output projection -> fp32 out
    {
        dim3 grid(D_MODEL / 128, NTOK / 128);
        tf32_gemm_bias<0><<<grid, 256, GEMM_SMEM_BYTES>>>(attn, woutt, bout, out, nullptr,
                                                          NTOK, D_MODEL, D_MODEL);
    }
}